// round 3
// baseline (speedup 1.0000x reference)
#include <cuda_runtime.h>
#include <math.h>

#define Bz 2
#define Sz 2048
#define Cz 1024
#define Hz 16
#define Dz 64
#define BHz 32

// Scratch (device globals: no allocation allowed in kernel_launch)
__device__ float g_q[BHz * Sz * Dz];
__device__ float g_k[BHz * Sz * Dz];
__device__ float g_v[BHz * Sz * Dz];
__device__ float g_cv[BHz * Sz * Dz];
__device__ float g_Mpart[4 * BHz * Dz * Dz];
__device__ float g_merged[Bz * Sz * Cz];

// ---------------------------------------------------------------------------
// Kernel 1: q/k/v projections.  GEMM (4096 x 1024) @ (1024 x 1024) + bias,
// output written directly in split-head layout (BH, S, D).
// 128x128 tile, BK=8, 256 threads, 8x8 micro-tile.
// blockIdx.z selects {q: y@wq, k: x@wk, v: y@wv}.
// ---------------------------------------------------------------------------
__global__ __launch_bounds__(256) void proj_kernel(
    const float* __restrict__ x, const float* __restrict__ y,
    const float* __restrict__ wq, const float* __restrict__ bq,
    const float* __restrict__ wk, const float* __restrict__ bk,
    const float* __restrict__ wv, const float* __restrict__ bv)
{
    const int which = blockIdx.z;
    const float* A    = (which == 1) ? x  : y;
    const float* W    = (which == 0) ? wq : (which == 1) ? wk : wv;
    const float* bias = (which == 0) ? bq : (which == 1) ? bk : bv;
    float* out        = (which == 0) ? g_q : (which == 1) ? g_k : g_v;

    __shared__ float As[8][132];   // [k][m], padded
    __shared__ float Bs[8][132];   // [k][n], padded

    const int tid = threadIdx.x;
    const int tx = tid & 15;
    const int ty = tid >> 4;
    const int m0 = blockIdx.y * 128;
    const int n0 = blockIdx.x * 128;

    const int aRow = tid >> 1;         // 0..127
    const int aCol = (tid & 1) * 4;    // 0 or 4
    const int bRow = tid >> 5;         // 0..7
    const int bCol = (tid & 31) * 4;   // 0..124

    float acc[8][8] = {};

    for (int k0 = 0; k0 < Cz; k0 += 8) {
        float4 a4 = *reinterpret_cast<const float4*>(&A[(size_t)(m0 + aRow) * Cz + k0 + aCol]);
        float4 b4 = *reinterpret_cast<const float4*>(&W[(size_t)(k0 + bRow) * Cz + n0 + bCol]);
        As[aCol + 0][aRow] = a4.x;
        As[aCol + 1][aRow] = a4.y;
        As[aCol + 2][aRow] = a4.z;
        As[aCol + 3][aRow] = a4.w;
        *reinterpret_cast<float4*>(&Bs[bRow][bCol]) = b4;
        __syncthreads();
        #pragma unroll
        for (int kk = 0; kk < 8; ++kk) {
            float4 a0 = *reinterpret_cast<const float4*>(&As[kk][ty * 8]);
            float4 a1 = *reinterpret_cast<const float4*>(&As[kk][ty * 8 + 4]);
            float4 b0 = *reinterpret_cast<const float4*>(&Bs[kk][tx * 8]);
            float4 b1 = *reinterpret_cast<const float4*>(&Bs[kk][tx * 8 + 4]);
            float ar[8] = {a0.x, a0.y, a0.z, a0.w, a1.x, a1.y, a1.z, a1.w};
            float br[8] = {b0.x, b0.y, b0.z, b0.w, b1.x, b1.y, b1.z, b1.w};
            #pragma unroll
            for (int i = 0; i < 8; ++i)
                #pragma unroll
                for (int j = 0; j < 8; ++j)
                    acc[i][j] = fmaf(ar[i], br[j], acc[i][j]);
        }
        __syncthreads();
    }

    float biasr[8];
    #pragma unroll
    for (int j = 0; j < 8; ++j) biasr[j] = bias[n0 + tx * 8 + j];

    #pragma unroll
    for (int i = 0; i < 8; ++i) {
        const int m  = m0 + ty * 8 + i;       // b*S + s
        const int bb = m >> 11;               // /S
        const int s  = m & (Sz - 1);
        #pragma unroll
        for (int j = 0; j < 8; ++j) {
            const int n = n0 + tx * 8 + j;    // h*D + d
            const int h = n >> 6;
            const int d = n & 63;
            out[(((size_t)bb * Hz + h) * Sz + s) * Dz + d] = acc[i][j] + biasr[j];
        }
    }
}

// ---------------------------------------------------------------------------
// Kernel 2: cv[bh] = tanh(t_mat[b]*wc[h] + bc[h]) @ v[bh]
// Per bh: GEMM M=2048(k) x N=64(d) x K=2048(s) with A generated on the fly.
// 128x64 tile, BK=8, 256 threads, 8x4 micro-tile.
// ---------------------------------------------------------------------------
__global__ __launch_bounds__(256) void cv_kernel(
    const float* __restrict__ t_mat,
    const float* __restrict__ wc,
    const float* __restrict__ bc)
{
    const int bh = blockIdx.z;
    const int b  = bh >> 4;
    const int h  = bh & 15;
    const float wch = wc[h];
    const float bch = bc[h];
    const float* Tp = t_mat + (size_t)b * Sz * Sz;
    const float* Vp = g_v  + (size_t)bh * Sz * Dz;

    __shared__ float As[8][132];   // [s][k-row]
    __shared__ float Bs[8][68];    // [s][d]

    const int tid = threadIdx.x;
    const int tx = tid & 15;       // cols (d), groups of 4 -> 64
    const int ty = tid >> 4;       // rows (k), groups of 8 -> 128
    const int k0 = blockIdx.y * 128;

    const int aRow = tid >> 1;
    const int aCol = (tid & 1) * 4;
    const int bRow = tid >> 4;     // only tid<128 used
    const int bCol = (tid & 15) * 4;

    float acc[8][4] = {};

    for (int s0 = 0; s0 < Sz; s0 += 8) {
        float4 a4 = *reinterpret_cast<const float4*>(&Tp[(size_t)(k0 + aRow) * Sz + s0 + aCol]);
        As[aCol + 0][aRow] = tanhf(fmaf(a4.x, wch, bch));
        As[aCol + 1][aRow] = tanhf(fmaf(a4.y, wch, bch));
        As[aCol + 2][aRow] = tanhf(fmaf(a4.z, wch, bch));
        As[aCol + 3][aRow] = tanhf(fmaf(a4.w, wch, bch));
        if (tid < 128) {
            float4 b4 = *reinterpret_cast<const float4*>(&Vp[(size_t)(s0 + bRow) * Dz + bCol]);
            *reinterpret_cast<float4*>(&Bs[bRow][bCol]) = b4;
        }
        __syncthreads();
        #pragma unroll
        for (int kk = 0; kk < 8; ++kk) {
            float4 a0 = *reinterpret_cast<const float4*>(&As[kk][ty * 8]);
            float4 a1 = *reinterpret_cast<const float4*>(&As[kk][ty * 8 + 4]);
            float4 b0 = *reinterpret_cast<const float4*>(&Bs[kk][tx * 4]);
            float ar[8] = {a0.x, a0.y, a0.z, a0.w, a1.x, a1.y, a1.z, a1.w};
            float br[4] = {b0.x, b0.y, b0.z, b0.w};
            #pragma unroll
            for (int i = 0; i < 8; ++i)
                #pragma unroll
                for (int j = 0; j < 4; ++j)
                    acc[i][j] = fmaf(ar[i], br[j], acc[i][j]);
        }
        __syncthreads();
    }

    float* Op = g_cv + (size_t)bh * Sz * Dz;
    #pragma unroll
    for (int i = 0; i < 8; ++i)
        #pragma unroll
        for (int j = 0; j < 4; ++j)
            Op[(size_t)(k0 + ty * 8 + i) * Dz + tx * 4 + j] = acc[i][j];
}

// ---------------------------------------------------------------------------
// Kernel 3: M[bh] = (1/sqrt(D)) * q[bh]^T @ cv[bh]  (64x64, K=2048)
// Split-K over 4 partials for occupancy; partials summed in att_kernel.
// ---------------------------------------------------------------------------
__global__ __launch_bounds__(256) void m_kernel()
{
    const int bh    = blockIdx.x;
    const int split = blockIdx.y;
    const float* Q   = g_q  + (size_t)bh * Sz * Dz;
    const float* CVp = g_cv + (size_t)bh * Sz * Dz;

    __shared__ float As[16][68];   // [s][d1]
    __shared__ float Bs[16][68];   // [s][d2]

    const int tid = threadIdx.x;
    const int tx = tid & 15;
    const int ty = tid >> 4;
    const int r  = tid >> 4;            // 0..15
    const int c4 = (tid & 15) * 4;      // 0..60

    float acc[4][4] = {};
    const int sBeg = split * (Sz / 4);

    for (int s0 = sBeg; s0 < sBeg + Sz / 4; s0 += 16) {
        *reinterpret_cast<float4*>(&As[r][c4]) =
            *reinterpret_cast<const float4*>(&Q[(size_t)(s0 + r) * Dz + c4]);
        *reinterpret_cast<float4*>(&Bs[r][c4]) =
            *reinterpret_cast<const float4*>(&CVp[(size_t)(s0 + r) * Dz + c4]);
        __syncthreads();
        #pragma unroll
        for (int kk = 0; kk < 16; ++kk) {
            float4 a = *reinterpret_cast<const float4*>(&As[kk][ty * 4]);
            float4 b = *reinterpret_cast<const float4*>(&Bs[kk][tx * 4]);
            float ar[4] = {a.x, a.y, a.z, a.w};
            float br[4] = {b.x, b.y, b.z, b.w};
            #pragma unroll
            for (int i = 0; i < 4; ++i)
                #pragma unroll
                for (int j = 0; j < 4; ++j)
                    acc[i][j] = fmaf(ar[i], br[j], acc[i][j]);
        }
        __syncthreads();
    }

    float* Mp = g_Mpart + ((size_t)split * BHz + bh) * Dz * Dz;
    #pragma unroll
    for (int i = 0; i < 4; ++i)
        #pragma unroll
        for (int j = 0; j < 4; ++j)
            Mp[(ty * 4 + i) * Dz + tx * 4 + j] = acc[i][j] * 0.125f;  // 1/sqrt(64)
}

// ---------------------------------------------------------------------------
// Kernel 4: att[bh] = k[bh] @ M[bh], written into merged (B,S,C) layout.
// 64x64 output tile, K=64 fully in smem (sums the 4 M split-K partials).
// ---------------------------------------------------------------------------
__global__ __launch_bounds__(256) void att_kernel()
{
    const int bh = blockIdx.z;
    const int b  = bh >> 4;
    const int h  = bh & 15;
    const int s0 = blockIdx.y * 64;
    const float* Kp = g_k + (size_t)bh * Sz * Dz;

    __shared__ float Ms[Dz * Dz];
    __shared__ float As[16][68];

    const int tid = threadIdx.x;
    const int tx = tid & 15;
    const int ty = tid >> 4;

    // Sum 4 split-K partials of M into shared memory
    const float4* P0 = reinterpret_cast<const float4*>(g_Mpart + ((size_t)0 * BHz + bh) * Dz * Dz);
    const float4* P1 = reinterpret_cast<const float4*>(g_Mpart + ((size_t)1 * BHz + bh) * Dz * Dz);
    const float4* P2 = reinterpret_cast<const float4*>(g_Mpart + ((size_t)2 * BHz + bh) * Dz * Dz);
    const float4* P3 = reinterpret_cast<const float4*>(g_Mpart + ((size_t)3 * BHz + bh) * Dz * Dz);
    #pragma unroll
    for (int it = 0; it < 4; ++it) {
        int fi = it * 256 + tid;
        float4 a = P0[fi], bb4 = P1[fi], c = P2[fi], d = P3[fi];
        float4 r;
        r.x = a.x + bb4.x + c.x + d.x;
        r.y = a.y + bb4.y + c.y + d.y;
        r.z = a.z + bb4.z + c.z + d.z;
        r.w = a.w + bb4.w + c.w + d.w;
        reinterpret_cast<float4*>(Ms)[fi] = r;
    }
    __syncthreads();

    const int aRow = tid >> 2;        // 0..63
    const int aCol = (tid & 3) * 4;   // 0..12

    float acc[4][4] = {};
    #pragma unroll
    for (int kb = 0; kb < 4; ++kb) {
        float4 a4 = *reinterpret_cast<const float4*>(&Kp[(size_t)(s0 + aRow) * Dz + kb * 16 + aCol]);
        As[aCol + 0][aRow] = a4.x;
        As[aCol + 1][aRow] = a4.y;
        As[aCol + 2][aRow] = a4.z;
        As[aCol + 3][aRow] = a4.w;
        __syncthreads();
        #pragma unroll
        for (int kk = 0; kk < 16; ++kk) {
            float4 a = *reinterpret_cast<const float4*>(&As[kk][ty * 4]);
            float4 bm = *reinterpret_cast<const float4*>(&Ms[(kb * 16 + kk) * Dz + tx * 4]);
            float ar[4] = {a.x, a.y, a.z, a.w};
            float br[4] = {bm.x, bm.y, bm.z, bm.w};
            #pragma unroll
            for (int i = 0; i < 4; ++i)
                #pragma unroll
                for (int j = 0; j < 4; ++j)
                    acc[i][j] = fmaf(ar[i], br[j], acc[i][j]);
        }
        __syncthreads();
    }

    #pragma unroll
    for (int i = 0; i < 4; ++i)
        #pragma unroll
        for (int j = 0; j < 4; ++j)
            g_merged[((size_t)b * Sz + s0 + ty * 4 + i) * Cz + h * Dz + tx * 4 + j] = acc[i][j];
}

// ---------------------------------------------------------------------------
// Kernel 5: out = mish(merged @ wf + bf).  Same tiling as proj_kernel.
// ---------------------------------------------------------------------------
__device__ __forceinline__ float mish_f(float v)
{
    float sp = (v > 20.0f) ? v : log1pf(expf(v));
    return v * tanhf(sp);
}

__global__ __launch_bounds__(256) void final_kernel(
    const float* __restrict__ wf, const float* __restrict__ bf, float* __restrict__ out)
{
    __shared__ float As[8][132];
    __shared__ float Bs[8][132];

    const int tid = threadIdx.x;
    const int tx = tid & 15;
    const int ty = tid >> 4;
    const int m0 = blockIdx.y * 128;
    const int n0 = blockIdx.x * 128;

    const int aRow = tid >> 1;
    const int aCol = (tid & 1) * 4;
    const int bRow = tid >> 5;
    const int bCol = (tid & 31) * 4;

    float acc[8][8] = {};

    for (int k0 = 0; k0 < Cz; k0 += 8) {
        float4 a4 = *reinterpret_cast<const float4*>(&g_merged[(size_t)(m0 + aRow) * Cz + k0 + aCol]);
        float4 b4 = *reinterpret_cast<const float4*>(&wf[(size_t)(k0 + bRow) * Cz + n0 + bCol]);
        As[aCol + 0][aRow] = a4.x;
        As[aCol + 1][aRow] = a4.y;
        As[aCol + 2][aRow] = a4.z;
        As[aCol + 3][aRow] = a4.w;
        *reinterpret_cast<float4*>(&Bs[bRow][bCol]) = b4;
        __syncthreads();
        #pragma unroll
        for (int kk = 0; kk < 8; ++kk) {
            float4 a0 = *reinterpret_cast<const float4*>(&As[kk][ty * 8]);
            float4 a1 = *reinterpret_cast<const float4*>(&As[kk][ty * 8 + 4]);
            float4 b0 = *reinterpret_cast<const float4*>(&Bs[kk][tx * 8]);
            float4 b1 = *reinterpret_cast<const float4*>(&Bs[kk][tx * 8 + 4]);
            float ar[8] = {a0.x, a0.y, a0.z, a0.w, a1.x, a1.y, a1.z, a1.w};
            float br[8] = {b0.x, b0.y, b0.z, b0.w, b1.x, b1.y, b1.z, b1.w};
            #pragma unroll
            for (int i = 0; i < 8; ++i)
                #pragma unroll
                for (int j = 0; j < 8; ++j)
                    acc[i][j] = fmaf(ar[i], br[j], acc[i][j]);
        }
        __syncthreads();
    }

    float biasr[8];
    #pragma unroll
    for (int j = 0; j < 8; ++j) biasr[j] = bf[n0 + tx * 8 + j];

    #pragma unroll
    for (int i = 0; i < 8; ++i) {
        const int m = m0 + ty * 8 + i;
        #pragma unroll
        for (int j = 0; j < 8; ++j) {
            const int n = n0 + tx * 8 + j;
            out[(size_t)m * Cz + n] = mish_f(acc[i][j] + biasr[j]);
        }
    }
}

// ---------------------------------------------------------------------------
extern "C" void kernel_launch(void* const* d_in, const int* in_sizes, int n_in,
                              void* d_out, int out_size)
{
    const float* x  = (const float*)d_in[0];
    const float* y  = (const float*)d_in[1];
    const float* t  = (const float*)d_in[2];
    const float* wq = (const float*)d_in[3];
    const float* bq = (const float*)d_in[4];
    const float* wk = (const float*)d_in[5];
    const float* bk = (const float*)d_in[6];
    const float* wv = (const float*)d_in[7];
    const float* bv = (const float*)d_in[8];
    const float* wc = (const float*)d_in[9];
    const float* bc = (const float*)d_in[10];
    const float* wf = (const float*)d_in[11];
    const float* bf = (const float*)d_in[12];
    float* out = (float*)d_out;

    // q,k,v projections: (4096x1024)@(1024x1024) x3
    proj_kernel<<<dim3(Cz / 128, (Bz * Sz) / 128, 3), 256>>>(x, y, wq, bq, wk, bk, wv, bv);
    // cv = tanh(t*wc+bc) @ v  (c never materialized)
    cv_kernel<<<dim3(1, Sz / 128, BHz), 256>>>(t, wc, bc);
    // M = q^T @ cv / sqrt(D), split-K x4
    m_kernel<<<dim3(BHz, 4), 256>>>();
    // att = k @ M -> merged (B,S,C)
    att_kernel<<<dim3(1, Sz / 64, BHz), 256>>>();
    // out = mish(merged @ wf + bf)
    final_kernel<<<dim3(Cz / 128, (Bz * Sz) / 128), 256>>>(wf, bf, out);
}

// round 4
// speedup vs baseline: 1.9880x; 1.9880x over previous
#include <cuda_runtime.h>
#include <cuda_bf16.h>
#include <math.h>
#include <stdint.h>

#define Bz 2
#define Sz 2048
#define Cz 1024
#define Hz 16
#define Dz 64
#define BHz 32

// Scratch (device globals: no allocation allowed in kernel_launch)
__device__ float g_q[BHz * Sz * Dz];
__device__ float g_k[BHz * Sz * Dz];
__device__ float g_v[BHz * Sz * Dz];
__device__ float g_cv[BHz * Sz * Dz];
__device__ float g_Mpart[4 * BHz * Dz * Dz];
__device__ float g_merged[Bz * Sz * Cz];

// ---------------------------------------------------------------------------
// Tensor-core helpers (mma.sync m16n8k16 bf16, fp32 accum)
// ---------------------------------------------------------------------------
__device__ __forceinline__ uint32_t sptr(const void* p) {
    return (uint32_t)__cvta_generic_to_shared(p);
}
__device__ __forceinline__ void ldsm4(uint32_t* r, uint32_t a) {
    asm volatile("ldmatrix.sync.aligned.m8n8.x4.shared.b16 {%0,%1,%2,%3},[%4];"
                 : "=r"(r[0]), "=r"(r[1]), "=r"(r[2]), "=r"(r[3]) : "r"(a));
}
__device__ __forceinline__ void ldsm4t(uint32_t* r, uint32_t a) {
    asm volatile("ldmatrix.sync.aligned.m8n8.x4.trans.shared.b16 {%0,%1,%2,%3},[%4];"
                 : "=r"(r[0]), "=r"(r[1]), "=r"(r[2]), "=r"(r[3]) : "r"(a));
}
__device__ __forceinline__ void mma16816(float* d, const uint32_t* a, const uint32_t* b) {
    asm volatile("mma.sync.aligned.m16n8k16.row.col.f32.bf16.bf16.f32 "
                 "{%0,%1,%2,%3},{%4,%5,%6,%7},{%8,%9},{%0,%1,%2,%3};"
                 : "+f"(d[0]), "+f"(d[1]), "+f"(d[2]), "+f"(d[3])
                 : "r"(a[0]), "r"(a[1]), "r"(a[2]), "r"(a[3]), "r"(b[0]), "r"(b[1]));
}
// Split fp32 pair into (hi,lo) bf16x2 packed registers (low 16 bits = first elem)
__device__ __forceinline__ void split_pack(float x, float y, uint32_t& hi, uint32_t& lo) {
    __nv_bfloat16 hx = __float2bfloat16_rn(x), hy = __float2bfloat16_rn(y);
    __nv_bfloat16 lx = __float2bfloat16_rn(x - __bfloat162float(hx));
    __nv_bfloat16 ly = __float2bfloat16_rn(y - __bfloat162float(hy));
    hi = ((uint32_t)__bfloat16_as_ushort(hy) << 16) | (uint32_t)__bfloat16_as_ushort(hx);
    lo = ((uint32_t)__bfloat16_as_ushort(ly) << 16) | (uint32_t)__bfloat16_as_ushort(lx);
}
__device__ __forceinline__ float tanh_fast(float x) {
    float xc = fminf(fmaxf(x, -12.0f), 12.0f);
    float e = __expf(2.0f * xc);
    return __fdividef(e - 1.0f, e + 1.0f);
}
__device__ __forceinline__ float mish_f(float v) {
    float sp = (v > 20.0f) ? v : log1pf(expf(v));
    return v * tanhf(sp);
}

#define PA 40    // A smem pitch in bf16 elems (32 + 8 pad -> conflict-free LDSM)
#define PB 136   // B smem pitch in bf16 elems (128 + 8 pad)
#define PT 40    // t tile pitch in fp32
#define PV 72    // v tile pitch in bf16 (64 + 8 pad)

// ---------------------------------------------------------------------------
// Kernel 1: q/k/v projections via bf16-split tensor cores.
// (4096 x 1024) @ (1024 x 1024) + bias, output in split-head layout.
// 128x128 block tile, k-step 32, 8 warps (2m x 4n), warp tile 64x32.
// ---------------------------------------------------------------------------
__global__ __launch_bounds__(256, 1) void proj_mma(
    const float* __restrict__ x, const float* __restrict__ y,
    const float* __restrict__ wq, const float* __restrict__ bq,
    const float* __restrict__ wk, const float* __restrict__ bk,
    const float* __restrict__ wv, const float* __restrict__ bv)
{
    const int which = blockIdx.z;
    const float* A    = (which == 1) ? x  : y;
    const float* W    = (which == 0) ? wq : (which == 1) ? wk : wv;
    const float* bias = (which == 0) ? bq : (which == 1) ? bk : bv;
    float* out        = (which == 0) ? g_q : (which == 1) ? g_k : g_v;

    __shared__ __align__(16) unsigned short Ash[128 * PA], Asl[128 * PA];
    __shared__ __align__(16) unsigned short Bsh[32 * PB],  Bsl[32 * PB];

    const int tid  = threadIdx.x;
    const int lane = tid & 31;
    const int wid  = tid >> 5;
    const int wm   = wid & 1;          // 0..1
    const int wn   = wid >> 1;         // 0..3
    const int m0   = blockIdx.y * 128;
    const int n0   = blockIdx.x * 128;

    float4 aS[4], bS[4];
    const int aRow = tid >> 3, aCol = (tid & 7) << 2;     // A: 32 rows/pass x 4 passes
    const int bRow = tid >> 5, bCol = (tid & 31) << 2;    // B: 8 rows/pass x 4 passes

    // preload k0 = 0
    #pragma unroll
    for (int r = 0; r < 4; ++r) {
        aS[r] = *(const float4*)&A[(size_t)(m0 + r * 32 + aRow) * Cz + aCol];
        bS[r] = *(const float4*)&W[(size_t)(r * 8 + bRow) * Cz + n0 + bCol];
    }

    float d[4][4][4] = {};

    for (int k0 = 0; k0 < Cz; k0 += 32) {
        // stage regs -> smem (convert to bf16 hi/lo)
        #pragma unroll
        for (int r = 0; r < 4; ++r) {
            uint32_t h0, l0, h1, l1;
            int row = r * 32 + aRow;
            split_pack(aS[r].x, aS[r].y, h0, l0);
            split_pack(aS[r].z, aS[r].w, h1, l1);
            *(uint2*)&Ash[row * PA + aCol] = make_uint2(h0, h1);
            *(uint2*)&Asl[row * PA + aCol] = make_uint2(l0, l1);
            int brow = r * 8 + bRow;
            split_pack(bS[r].x, bS[r].y, h0, l0);
            split_pack(bS[r].z, bS[r].w, h1, l1);
            *(uint2*)&Bsh[brow * PB + bCol] = make_uint2(h0, h1);
            *(uint2*)&Bsl[brow * PB + bCol] = make_uint2(l0, l1);
        }
        __syncthreads();

        // prefetch next tile
        if (k0 + 32 < Cz) {
            #pragma unroll
            for (int r = 0; r < 4; ++r) {
                aS[r] = *(const float4*)&A[(size_t)(m0 + r * 32 + aRow) * Cz + k0 + 32 + aCol];
                bS[r] = *(const float4*)&W[(size_t)(k0 + 32 + r * 8 + bRow) * Cz + n0 + bCol];
            }
        }

        #pragma unroll
        for (int k16 = 0; k16 < 32; k16 += 16) {
            uint32_t ah[4][4], al[4][4];
            #pragma unroll
            for (int mf = 0; mf < 4; ++mf) {
                int mr = wm * 64 + mf * 16 + (lane & 15);
                int kc = k16 + ((lane >> 4) << 3);
                ldsm4(ah[mf], sptr(&Ash[mr * PA + kc]));
                ldsm4(al[mf], sptr(&Asl[mr * PA + kc]));
            }
            uint32_t bh[4][2], bl[4][2];
            #pragma unroll
            for (int nf2 = 0; nf2 < 2; ++nf2) {
                int kr = k16 + (lane & 7) + ((lane >> 3) & 1) * 8;
                int nc = wn * 32 + nf2 * 16 + ((lane >> 4) << 3);
                uint32_t t[4];
                ldsm4t(t, sptr(&Bsh[kr * PB + nc]));
                bh[nf2 * 2][0] = t[0]; bh[nf2 * 2][1] = t[1];
                bh[nf2 * 2 + 1][0] = t[2]; bh[nf2 * 2 + 1][1] = t[3];
                ldsm4t(t, sptr(&Bsl[kr * PB + nc]));
                bl[nf2 * 2][0] = t[0]; bl[nf2 * 2][1] = t[1];
                bl[nf2 * 2 + 1][0] = t[2]; bl[nf2 * 2 + 1][1] = t[3];
            }
            #pragma unroll
            for (int mf = 0; mf < 4; ++mf)
                #pragma unroll
                for (int nf = 0; nf < 4; ++nf) {
                    mma16816(d[mf][nf], ah[mf], bh[nf]);
                    mma16816(d[mf][nf], ah[mf], bl[nf]);
                    mma16816(d[mf][nf], al[mf], bh[nf]);
                }
        }
        __syncthreads();
    }

    // epilogue: +bias, write split-head layout (BH, S, D)
    #pragma unroll
    for (int mf = 0; mf < 4; ++mf)
        #pragma unroll
        for (int nf = 0; nf < 4; ++nf) {
            int mr = m0 + wm * 64 + mf * 16 + (lane >> 2);
            int nc = n0 + wn * 32 + nf * 8 + ((lane & 3) << 1);
            float2 bv2 = *(const float2*)&bias[nc];
            int bb = mr >> 11, s = mr & (Sz - 1);
            int h = nc >> 6, dd = nc & 63;
            float* op = &out[(((size_t)bb * Hz + h) * Sz + s) * Dz + dd];
            *(float2*)op = make_float2(d[mf][nf][0] + bv2.x, d[mf][nf][1] + bv2.y);
            float* op2 = &out[(((size_t)bb * Hz + h) * Sz + (s + 8)) * Dz + dd];
            *(float2*)op2 = make_float2(d[mf][nf][2] + bv2.x, d[mf][nf][3] + bv2.y);
        }
}

// ---------------------------------------------------------------------------
// Kernel 2: cv[bh] = tanh(t*wc[h]+bc[h]) @ v[bh], tensor cores.
// Grid (hgroup=8, ktile=16, b=2). Each CTA: 128 k-rows x 2 heads x 64 d,
// K-dim = s = 2048, s-step 32. A fragments built in registers (tanh on the
// fly from shared fp32 t tile), v converted to bf16 hi/lo in smem.
// 8 warps: (h = wid/4) x (2m x 2n), warp tile 64x32.
// ---------------------------------------------------------------------------
__global__ __launch_bounds__(256, 1) void cv_mma(
    const float* __restrict__ t_mat,
    const float* __restrict__ wc,
    const float* __restrict__ bc)
{
    const int hg = blockIdx.x, kt = blockIdx.y, b = blockIdx.z;

    __shared__ __align__(16) float Ts[128 * PT];
    __shared__ __align__(16) unsigned short Vsh[2][32 * PV], Vsl[2][32 * PV];

    const int tid  = threadIdx.x;
    const int lane = tid & 31;
    const int wid  = tid >> 5;
    const int hh   = wid >> 2;           // 0..1 head within group
    const int rem  = wid & 3;
    const int m0w  = (rem >> 1) * 64;
    const int n0w  = (rem & 1) * 32;
    const int h    = hg * 2 + hh;
    const float wch = wc[h];
    const float bch = bc[h];

    const float* Tp  = t_mat + (size_t)b * Sz * Sz + (size_t)(kt * 128) * Sz;
    const float* Vp0 = g_v + ((size_t)(b * Hz + hg * 2) * Sz) * Dz;

    const int tRow = tid >> 3, tCol = (tid & 7) << 2;

    float4 tS[4], vS[4];
    #pragma unroll
    for (int r = 0; r < 4; ++r) {
        tS[r] = *(const float4*)&Tp[(size_t)(r * 32 + tRow) * Sz + tCol];
        int idx = r * 256 + tid;
        int vh = idx >> 9, vrem = idx & 511;
        vS[r] = *(const float4*)&Vp0[(size_t)vh * Sz * Dz + (size_t)(vrem >> 4) * Dz + ((idx & 15) << 2)];
    }

    float d[4][4][4] = {};

    for (int s0 = 0; s0 < Sz; s0 += 32) {
        #pragma unroll
        for (int r = 0; r < 4; ++r) {
            *(float4*)&Ts[(r * 32 + tRow) * PT + tCol] = tS[r];
            int idx = r * 256 + tid;
            int vh = idx >> 9, vrow = (idx & 511) >> 4, vcol = (idx & 15) << 2;
            uint32_t h0, l0, h1, l1;
            split_pack(vS[r].x, vS[r].y, h0, l0);
            split_pack(vS[r].z, vS[r].w, h1, l1);
            *(uint2*)&Vsh[vh][vrow * PV + vcol] = make_uint2(h0, h1);
            *(uint2*)&Vsl[vh][vrow * PV + vcol] = make_uint2(l0, l1);
        }
        __syncthreads();

        if (s0 + 32 < Sz) {
            #pragma unroll
            for (int r = 0; r < 4; ++r) {
                tS[r] = *(const float4*)&Tp[(size_t)(r * 32 + tRow) * Sz + s0 + 32 + tCol];
                int idx = r * 256 + tid;
                int vh = idx >> 9, vrem = idx & 511;
                vS[r] = *(const float4*)&Vp0[(size_t)vh * Sz * Dz +
                                             (size_t)(s0 + 32 + (vrem >> 4)) * Dz + ((idx & 15) << 2)];
            }
        }

        #pragma unroll
        for (int k16 = 0; k16 < 32; k16 += 16) {
            uint32_t ah[4][4], al[4][4];
            #pragma unroll
            for (int mf = 0; mf < 4; ++mf) {
                int r0 = m0w + mf * 16 + (lane >> 2);
                int c0 = k16 + ((lane & 3) << 1);
                float2 t00 = *(const float2*)&Ts[r0 * PT + c0];
                float2 t10 = *(const float2*)&Ts[(r0 + 8) * PT + c0];
                float2 t01 = *(const float2*)&Ts[r0 * PT + c0 + 8];
                float2 t11 = *(const float2*)&Ts[(r0 + 8) * PT + c0 + 8];
                split_pack(tanh_fast(fmaf(t00.x, wch, bch)), tanh_fast(fmaf(t00.y, wch, bch)),
                           ah[mf][0], al[mf][0]);
                split_pack(tanh_fast(fmaf(t10.x, wch, bch)), tanh_fast(fmaf(t10.y, wch, bch)),
                           ah[mf][1], al[mf][1]);
                split_pack(tanh_fast(fmaf(t01.x, wch, bch)), tanh_fast(fmaf(t01.y, wch, bch)),
                           ah[mf][2], al[mf][2]);
                split_pack(tanh_fast(fmaf(t11.x, wch, bch)), tanh_fast(fmaf(t11.y, wch, bch)),
                           ah[mf][3], al[mf][3]);
            }
            uint32_t bh[4][2], bl[4][2];
            #pragma unroll
            for (int nf2 = 0; nf2 < 2; ++nf2) {
                int kr = k16 + (lane & 7) + ((lane >> 3) & 1) * 8;
                int nc = n0w + nf2 * 16 + ((lane >> 4) << 3);
                uint32_t t[4];
                ldsm4t(t, sptr(&Vsh[hh][kr * PV + nc]));
                bh[nf2 * 2][0] = t[0]; bh[nf2 * 2][1] = t[1];
                bh[nf2 * 2 + 1][0] = t[2]; bh[nf2 * 2 + 1][1] = t[3];
                ldsm4t(t, sptr(&Vsl[hh][kr * PV + nc]));
                bl[nf2 * 2][0] = t[0]; bl[nf2 * 2][1] = t[1];
                bl[nf2 * 2 + 1][0] = t[2]; bl[nf2 * 2 + 1][1] = t[3];
            }
            #pragma unroll
            for (int mf = 0; mf < 4; ++mf)
                #pragma unroll
                for (int nf = 0; nf < 4; ++nf) {
                    mma16816(d[mf][nf], ah[mf], bh[nf]);
                    mma16816(d[mf][nf], ah[mf], bl[nf]);
                    mma16816(d[mf][nf], al[mf], bh[nf]);
                }
        }
        __syncthreads();
    }

    float* Op = g_cv + ((size_t)(b * Hz + h) * Sz) * Dz;
    #pragma unroll
    for (int mf = 0; mf < 4; ++mf)
        #pragma unroll
        for (int nf = 0; nf < 4; ++nf) {
            int row = kt * 128 + m0w + mf * 16 + (lane >> 2);
            int dd  = n0w + nf * 8 + ((lane & 3) << 1);
            *(float2*)&Op[(size_t)row * Dz + dd] = make_float2(d[mf][nf][0], d[mf][nf][1]);
            *(float2*)&Op[(size_t)(row + 8) * Dz + dd] = make_float2(d[mf][nf][2], d[mf][nf][3]);
        }
}

// ---------------------------------------------------------------------------
// Kernel 3: M[bh] = (1/sqrt(D)) * q[bh]^T @ cv[bh]  (64x64, K=2048), split-K x4
// ---------------------------------------------------------------------------
__global__ __launch_bounds__(256) void m_kernel()
{
    const int bh    = blockIdx.x;
    const int split = blockIdx.y;
    const float* Q   = g_q  + (size_t)bh * Sz * Dz;
    const float* CVp = g_cv + (size_t)bh * Sz * Dz;

    __shared__ float As[16][68];
    __shared__ float Bs[16][68];

    const int tid = threadIdx.x;
    const int tx = tid & 15;
    const int ty = tid >> 4;
    const int r  = tid >> 4;
    const int c4 = (tid & 15) * 4;

    float acc[4][4] = {};
    const int sBeg = split * (Sz / 4);

    for (int s0 = sBeg; s0 < sBeg + Sz / 4; s0 += 16) {
        *reinterpret_cast<float4*>(&As[r][c4]) =
            *reinterpret_cast<const float4*>(&Q[(size_t)(s0 + r) * Dz + c4]);
        *reinterpret_cast<float4*>(&Bs[r][c4]) =
            *reinterpret_cast<const float4*>(&CVp[(size_t)(s0 + r) * Dz + c4]);
        __syncthreads();
        #pragma unroll
        for (int kk = 0; kk < 16; ++kk) {
            float4 a = *reinterpret_cast<const float4*>(&As[kk][ty * 4]);
            float4 b = *reinterpret_cast<const float4*>(&Bs[kk][tx * 4]);
            float ar[4] = {a.x, a.y, a.z, a.w};
            float br[4] = {b.x, b.y, b.z, b.w};
            #pragma unroll
            for (int i = 0; i < 4; ++i)
                #pragma unroll
                for (int j = 0; j < 4; ++j)
                    acc[i][j] = fmaf(ar[i], br[j], acc[i][j]);
        }
        __syncthreads();
    }

    float* Mp = g_Mpart + ((size_t)split * BHz + bh) * Dz * Dz;
    #pragma unroll
    for (int i = 0; i < 4; ++i)
        #pragma unroll
        for (int j = 0; j < 4; ++j)
            Mp[(ty * 4 + i) * Dz + tx * 4 + j] = acc[i][j] * 0.125f;
}

// ---------------------------------------------------------------------------
// Kernel 4: att[bh] = k[bh] @ M[bh] -> merged (B,S,C)
// ---------------------------------------------------------------------------
__global__ __launch_bounds__(256) void att_kernel()
{
    const int bh = blockIdx.z;
    const int b  = bh >> 4;
    const int h  = bh & 15;
    const int s0 = blockIdx.y * 64;
    const float* Kp = g_k + (size_t)bh * Sz * Dz;

    __shared__ float Ms[Dz * Dz];
    __shared__ float As[16][68];

    const int tid = threadIdx.x;
    const int tx = tid & 15;
    const int ty = tid >> 4;

    const float4* P0 = reinterpret_cast<const float4*>(g_Mpart + ((size_t)0 * BHz + bh) * Dz * Dz);
    const float4* P1 = reinterpret_cast<const float4*>(g_Mpart + ((size_t)1 * BHz + bh) * Dz * Dz);
    const float4* P2 = reinterpret_cast<const float4*>(g_Mpart + ((size_t)2 * BHz + bh) * Dz * Dz);
    const float4* P3 = reinterpret_cast<const float4*>(g_Mpart + ((size_t)3 * BHz + bh) * Dz * Dz);
    #pragma unroll
    for (int it = 0; it < 4; ++it) {
        int fi = it * 256 + tid;
        float4 a = P0[fi], bb4 = P1[fi], c = P2[fi], dd = P3[fi];
        float4 rr;
        rr.x = a.x + bb4.x + c.x + dd.x;
        rr.y = a.y + bb4.y + c.y + dd.y;
        rr.z = a.z + bb4.z + c.z + dd.z;
        rr.w = a.w + bb4.w + c.w + dd.w;
        reinterpret_cast<float4*>(Ms)[fi] = rr;
    }
    __syncthreads();

    const int aRow = tid >> 2;
    const int aCol = (tid & 3) * 4;

    float acc[4][4] = {};
    #pragma unroll
    for (int kb = 0; kb < 4; ++kb) {
        float4 a4 = *reinterpret_cast<const float4*>(&Kp[(size_t)(s0 + aRow) * Dz + kb * 16 + aCol]);
        As[aCol + 0][aRow] = a4.x;
        As[aCol + 1][aRow] = a4.y;
        As[aCol + 2][aRow] = a4.z;
        As[aCol + 3][aRow] = a4.w;
        __syncthreads();
        #pragma unroll
        for (int kk = 0; kk < 16; ++kk) {
            float4 a = *reinterpret_cast<const float4*>(&As[kk][ty * 4]);
            float4 bm = *reinterpret_cast<const float4*>(&Ms[(kb * 16 + kk) * Dz + tx * 4]);
            float ar[4] = {a.x, a.y, a.z, a.w};
            float br[4] = {bm.x, bm.y, bm.z, bm.w};
            #pragma unroll
            for (int i = 0; i < 4; ++i)
                #pragma unroll
                for (int j = 0; j < 4; ++j)
                    acc[i][j] = fmaf(ar[i], br[j], acc[i][j]);
        }
        __syncthreads();
    }

    #pragma unroll
    for (int i = 0; i < 4; ++i)
        #pragma unroll
        for (int j = 0; j < 4; ++j)
            g_merged[((size_t)b * Sz + s0 + ty * 4 + i) * Cz + h * Dz + tx * 4 + j] = acc[i][j];
}

// ---------------------------------------------------------------------------
// Kernel 5: out = mish(merged @ wf + bf) via bf16-split tensor cores.
// Same structure as proj_mma, mish epilogue, plain (B*S, C) output.
// ---------------------------------------------------------------------------
__global__ __launch_bounds__(256, 1) void final_mma(
    const float* __restrict__ wf, const float* __restrict__ bf, float* __restrict__ out)
{
    __shared__ __align__(16) unsigned short Ash[128 * PA], Asl[128 * PA];
    __shared__ __align__(16) unsigned short Bsh[32 * PB],  Bsl[32 * PB];

    const int tid  = threadIdx.x;
    const int lane = tid & 31;
    const int wid  = tid >> 5;
    const int wm   = wid & 1;
    const int wn   = wid >> 1;
    const int m0   = blockIdx.y * 128;
    const int n0   = blockIdx.x * 128;

    float4 aS[4], bS[4];
    const int aRow = tid >> 3, aCol = (tid & 7) << 2;
    const int bRow = tid >> 5, bCol = (tid & 31) << 2;

    #pragma unroll
    for (int r = 0; r < 4; ++r) {
        aS[r] = *(const float4*)&g_merged[(size_t)(m0 + r * 32 + aRow) * Cz + aCol];
        bS[r] = *(const float4*)&wf[(size_t)(r * 8 + bRow) * Cz + n0 + bCol];
    }

    float d[4][4][4] = {};

    for (int k0 = 0; k0 < Cz; k0 += 32) {
        #pragma unroll
        for (int r = 0; r < 4; ++r) {
            uint32_t h0, l0, h1, l1;
            int row = r * 32 + aRow;
            split_pack(aS[r].x, aS[r].y, h0, l0);
            split_pack(aS[r].z, aS[r].w, h1, l1);
            *(uint2*)&Ash[row * PA + aCol] = make_uint2(h0, h1);
            *(uint2*)&Asl[row * PA + aCol] = make_uint2(l0, l1);
            int brow = r * 8 + bRow;
            split_pack(bS[r].x, bS[r].y, h0, l0);
            split_pack(bS[r].z, bS[r].w, h1, l1);
            *(uint2*)&Bsh[brow * PB + bCol] = make_uint2(h0, h1);
            *(uint2*)&Bsl[brow * PB + bCol] = make_uint2(l0, l1);
        }
        __syncthreads();

        if (k0 + 32 < Cz) {
            #pragma unroll
            for (int r = 0; r < 4; ++r) {
                aS[r] = *(const float4*)&g_merged[(size_t)(m0 + r * 32 + aRow) * Cz + k0 + 32 + aCol];
                bS[r] = *(const float4*)&wf[(size_t)(k0 + 32 + r * 8 + bRow) * Cz + n0 + bCol];
            }
        }

        #pragma unroll
        for (int k16 = 0; k16 < 32; k16 += 16) {
            uint32_t ah[4][4], al[4][4];
            #pragma unroll
            for (int mf = 0; mf < 4; ++mf) {
                int mr = wm * 64 + mf * 16 + (lane & 15);
                int kc = k16 + ((lane >> 4) << 3);
                ldsm4(ah[mf], sptr(&Ash[mr * PA + kc]));
                ldsm4(al[mf], sptr(&Asl[mr * PA + kc]));
            }
            uint32_t bh[4][2], bl[4][2];
            #pragma unroll
            for (int nf2 = 0; nf2 < 2; ++nf2) {
                int kr = k16 + (lane & 7) + ((lane >> 3) & 1) * 8;
                int nc = wn * 32 + nf2 * 16 + ((lane >> 4) << 3);
                uint32_t t[4];
                ldsm4t(t, sptr(&Bsh[kr * PB + nc]));
                bh[nf2 * 2][0] = t[0]; bh[nf2 * 2][1] = t[1];
                bh[nf2 * 2 + 1][0] = t[2]; bh[nf2 * 2 + 1][1] = t[3];
                ldsm4t(t, sptr(&Bsl[kr * PB + nc]));
                bl[nf2 * 2][0] = t[0]; bl[nf2 * 2][1] = t[1];
                bl[nf2 * 2 + 1][0] = t[2]; bl[nf2 * 2 + 1][1] = t[3];
            }
            #pragma unroll
            for (int mf = 0; mf < 4; ++mf)
                #pragma unroll
                for (int nf = 0; nf < 4; ++nf) {
                    mma16816(d[mf][nf], ah[mf], bh[nf]);
                    mma16816(d[mf][nf], ah[mf], bl[nf]);
                    mma16816(d[mf][nf], al[mf], bh[nf]);
                }
        }
        __syncthreads();
    }

    #pragma unroll
    for (int mf = 0; mf < 4; ++mf)
        #pragma unroll
        for (int nf = 0; nf < 4; ++nf) {
            int mr = m0 + wm * 64 + mf * 16 + (lane >> 2);
            int nc = n0 + wn * 32 + nf * 8 + ((lane & 3) << 1);
            float2 bv2 = *(const float2*)&bf[nc];
            *(float2*)&out[(size_t)mr * Cz + nc] =
                make_float2(mish_f(d[mf][nf][0] + bv2.x), mish_f(d[mf][nf][1] + bv2.y));
            *(float2*)&out[(size_t)(mr + 8) * Cz + nc] =
                make_float2(mish_f(d[mf][nf][2] + bv2.x), mish_f(d[mf][nf][3] + bv2.y));
        }
}

// ---------------------------------------------------------------------------
extern "C" void kernel_launch(void* const* d_in, const int* in_sizes, int n_in,
                              void* d_out, int out_size)
{
    const float* x  = (const float*)d_in[0];
    const float* y  = (const float*)d_in[1];
    const float* t  = (const float*)d_in[2];
    const float* wq = (const float*)d_in[3];
    const float* bq = (const float*)d_in[4];
    const float* wk = (const float*)d_in[5];
    const float* bk = (const float*)d_in[6];
    const float* wv = (const float*)d_in[7];
    const float* bv = (const float*)d_in[8];
    const float* wc = (const float*)d_in[9];
    const float* bc = (const float*)d_in[10];
    const float* wf = (const float*)d_in[11];
    const float* bf = (const float*)d_in[12];
    float* out = (float*)d_out;

    // q,k,v projections (tensor cores, bf16 split)
    proj_mma<<<dim3(Cz / 128, (Bz * Sz) / 128, 3), 256>>>(x, y, wq, bq, wk, bk, wv, bv);
    // cv = tanh(t*wc+bc) @ v  (tensor cores; c never materialized)
    cv_mma<<<dim3(Hz / 2, Sz / 128, Bz), 256>>>(t, wc, bc);
    // M = q^T @ cv / sqrt(D), split-K x4
    m_kernel<<<dim3(BHz, 4), 256>>>();
    // att = k @ M -> merged
    att_kernel<<<dim3(1, Sz / 64, BHz), 256>>>();
    // out = mish(merged @ wf + bf)
    final_mma<<<dim3(Cz / 128, (Bz * Sz) / 128), 256>>>(wf, bf, out);
}

// round 7
// speedup vs baseline: 2.0896x; 1.0511x over previous
#include <cuda_runtime.h>
#include <cuda_bf16.h>
#include <math.h>
#include <stdint.h>

#define Bz 2
#define Sz 2048
#define Cz 1024
#define Hz 16
#define Dz 64
#define BHz 32

typedef unsigned short u16;

// ---------------------------------------------------------------------------
// Scratch (device globals: no allocation allowed in kernel_launch)
// ---------------------------------------------------------------------------
__device__ float g_q[BHz * Sz * Dz];
__device__ float g_k[BHz * Sz * Dz];
__device__ float g_cv[BHz * Sz * Dz];
__device__ float g_Mpart[4 * BHz * Dz * Dz];

// bf16 hi/lo planes
__device__ u16 g_xh[Bz * Sz * Cz], g_xl[Bz * Sz * Cz];
__device__ u16 g_yh[Bz * Sz * Cz], g_yl[Bz * Sz * Cz];
__device__ u16 g_wqh[Cz * Cz], g_wql[Cz * Cz];
__device__ u16 g_wkh[Cz * Cz], g_wkl[Cz * Cz];
__device__ u16 g_wvh[Cz * Cz], g_wvl[Cz * Cz];
__device__ u16 g_wfh[Cz * Cz], g_wfl[Cz * Cz];
__device__ u16 g_vh[BHz * Sz * Dz], g_vl[BHz * Sz * Dz];
__device__ u16 g_mh[Bz * Sz * Cz], g_ml[Bz * Sz * Cz];

// ---------------------------------------------------------------------------
// Helpers
// ---------------------------------------------------------------------------
__device__ __forceinline__ uint32_t smem_u32(const void* p) {
    return (uint32_t)__cvta_generic_to_shared(p);
}
__device__ __forceinline__ void ldsm4(uint32_t* r, uint32_t a) {
    asm volatile("ldmatrix.sync.aligned.m8n8.x4.shared.b16 {%0,%1,%2,%3},[%4];"
                 : "=r"(r[0]), "=r"(r[1]), "=r"(r[2]), "=r"(r[3]) : "r"(a));
}
__device__ __forceinline__ void ldsm4t(uint32_t* r, uint32_t a) {
    asm volatile("ldmatrix.sync.aligned.m8n8.x4.trans.shared.b16 {%0,%1,%2,%3},[%4];"
                 : "=r"(r[0]), "=r"(r[1]), "=r"(r[2]), "=r"(r[3]) : "r"(a));
}
__device__ __forceinline__ void mma16816(float* d, const uint32_t* a, const uint32_t* b) {
    asm volatile("mma.sync.aligned.m16n8k16.row.col.f32.bf16.bf16.f32 "
                 "{%0,%1,%2,%3},{%4,%5,%6,%7},{%8,%9},{%0,%1,%2,%3};"
                 : "+f"(d[0]), "+f"(d[1]), "+f"(d[2]), "+f"(d[3])
                 : "r"(a[0]), "r"(a[1]), "r"(a[2]), "r"(a[3]), "r"(b[0]), "r"(b[1]));
}
__device__ __forceinline__ void cpa16(uint32_t s, const void* g) {
    asm volatile("cp.async.cg.shared.global [%0], [%1], 16;" :: "r"(s), "l"(g));
}
__device__ __forceinline__ void cpa_commit() {
    asm volatile("cp.async.commit_group;" ::: "memory");
}
__device__ __forceinline__ void cpa_wait1() {
    asm volatile("cp.async.wait_group 1;" ::: "memory");
}
__device__ __forceinline__ void split_pack(float x, float y, uint32_t& hi, uint32_t& lo) {
    __nv_bfloat16 hx = __float2bfloat16_rn(x), hy = __float2bfloat16_rn(y);
    __nv_bfloat16 lx = __float2bfloat16_rn(x - __bfloat162float(hx));
    __nv_bfloat16 ly = __float2bfloat16_rn(y - __bfloat162float(hy));
    hi = ((uint32_t)__bfloat16_as_ushort(hy) << 16) | (uint32_t)__bfloat16_as_ushort(hx);
    lo = ((uint32_t)__bfloat16_as_ushort(ly) << 16) | (uint32_t)__bfloat16_as_ushort(lx);
}
__device__ __forceinline__ float tanh_fast(float x) {
    float xc = fminf(fmaxf(x, -12.0f), 12.0f);
    float e = __expf(2.0f * xc);
    return __fdividef(e - 1.0f, e + 1.0f);
}
__device__ __forceinline__ float mish_f(float v) {
    float sp = (v > 20.0f) ? v : log1pf(expf(v));
    return v * tanhf(sp);
}

// ---------------------------------------------------------------------------
// Kernel 0: fp32 -> bf16 hi/lo plane conversion (grid-stride over float4)
// ---------------------------------------------------------------------------
__global__ __launch_bounds__(256) void cvt_kernel(
    const float* __restrict__ src, u16* __restrict__ ph, u16* __restrict__ pl, int n)
{
    int i = (blockIdx.x * 256 + threadIdx.x) * 4;
    if (i < n) {
        float4 v = *(const float4*)&src[i];
        uint32_t h0, l0, h1, l1;
        split_pack(v.x, v.y, h0, l0);
        split_pack(v.z, v.w, h1, l1);
        *(uint2*)&ph[i] = make_uint2(h0, h1);
        *(uint2*)&pl[i] = make_uint2(l0, l1);
    }
}

// ---------------------------------------------------------------------------
// Shared-memory geometry
// ---------------------------------------------------------------------------
#define PA 40     // A tile pitch (32 + 8 pad), bf16 elems
#define PB 136    // B tile pitch (128 + 8 pad)
#define PV 72     // v tile pitch (64 + 8 pad)

#define PRJ_APB   10240                 // one A plane: 128*40*2
#define PRJ_BOFF  20480                 // B planes start
#define PRJ_BPB   8704                  // one B plane: 32*136*2
#define PRJ_STRIDE 37888
#define PROJ_SMEM (2 * PRJ_STRIDE)

#define CV_APB   10240                  // one A plane: 128*40*2
#define CV_ABLK  20480                  // per-head A block (hi+lo)
#define CV_BOFF  40960
#define CV_BPB   4608                   // one B plane: 32*72*2
#define CV_BBLK  9216                   // per-head B block
#define CV_STRIDE 59392
#define CV_SMEM  (2 * CV_STRIDE)

// stage one (A 128x32, B 32x128) chunk pair of hi/lo planes via cp.async
__device__ __forceinline__ void stage_prj(
    const u16* __restrict__ Ah, const u16* __restrict__ Al,
    const u16* __restrict__ Bh, const u16* __restrict__ Bl,
    uint32_t base, int m0, int n0, int k0, int tid)
{
    int row = tid >> 1, half = tid & 1;
    size_t ga = (size_t)(m0 + row) * Cz + k0 + half * 16;
    uint32_t da = base + (row * PA + half * 16) * 2;
    cpa16(da, Ah + ga);               cpa16(da + 16, Ah + ga + 8);
    cpa16(da + PRJ_APB, Al + ga);     cpa16(da + PRJ_APB + 16, Al + ga + 8);
    int br = tid >> 3, seg = tid & 7;
    size_t gb = (size_t)(k0 + br) * Cz + n0 + seg * 8;
    uint32_t db = base + PRJ_BOFF + (br * PB + seg * 8) * 2;
    cpa16(db, Bh + gb);               cpa16(db + 128, Bh + gb + 64);
    cpa16(db + PRJ_BPB, Bl + gb);     cpa16(db + PRJ_BPB + 128, Bl + gb + 64);
}

// one 32-k chunk of 3-term split MMAs (warp tile 64x32, frags 4x4)
__device__ __forceinline__ void mma_chunk(
    float d[4][4][4], uint32_t Ah, uint32_t Al, uint32_t Bh, uint32_t Bl,
    int pitchB, int wm64, int wn32, int lane)
{
    #pragma unroll
    for (int k16 = 0; k16 < 32; k16 += 16) {
        uint32_t ah[4][4], al[4][4];
        #pragma unroll
        for (int mf = 0; mf < 4; ++mf) {
            int mr = wm64 + mf * 16 + (lane & 15);
            int kc = k16 + ((lane >> 4) << 3);
            ldsm4(ah[mf], Ah + (mr * PA + kc) * 2);
            ldsm4(al[mf], Al + (mr * PA + kc) * 2);
        }
        uint32_t bh[4][2], bl[4][2];
        #pragma unroll
        for (int nf2 = 0; nf2 < 2; ++nf2) {
            int kr = k16 + (lane & 7) + ((lane >> 3) & 1) * 8;
            int nc = wn32 + nf2 * 16 + ((lane >> 4) << 3);
            uint32_t t[4];
            ldsm4t(t, Bh + (kr * pitchB + nc) * 2);
            bh[nf2 * 2][0] = t[0]; bh[nf2 * 2][1] = t[1];
            bh[nf2 * 2 + 1][0] = t[2]; bh[nf2 * 2 + 1][1] = t[3];
            ldsm4t(t, Bl + (kr * pitchB + nc) * 2);
            bl[nf2 * 2][0] = t[0]; bl[nf2 * 2][1] = t[1];
            bl[nf2 * 2 + 1][0] = t[2]; bl[nf2 * 2 + 1][1] = t[3];
        }
        #pragma unroll
        for (int mf = 0; mf < 4; ++mf)
            #pragma unroll
            for (int nf = 0; nf < 4; ++nf) {
                mma16816(d[mf][nf], ah[mf], bh[nf]);
                mma16816(d[mf][nf], ah[mf], bl[nf]);
                mma16816(d[mf][nf], al[mf], bh[nf]);
            }
    }
}

// ---------------------------------------------------------------------------
// Kernel 1: q/k/v projections.  Pure cp.async + ldmatrix + mma mainloop.
// CTA 128x128, chunk k=32, 8 warps (2m x 4n).  which: 0=q(y,wq) 1=k(x,wk) 2=v(y,wv)
// q,k written fp32 split-head; v written as bf16 hi/lo planes.
// ---------------------------------------------------------------------------
__global__ __launch_bounds__(256, 1) void proj_mma(
    const float* __restrict__ bq, const float* __restrict__ bk,
    const float* __restrict__ bv)
{
    extern __shared__ char smc[];
    const uint32_t sb = smem_u32(smc);
    const int tid = threadIdx.x, lane = tid & 31, wid = tid >> 5;
    const int wm = wid & 1, wn = wid >> 1;
    const int which = blockIdx.z;
    const u16* Ahg = (which == 1) ? g_xh : g_yh;
    const u16* Alg = (which == 1) ? g_xl : g_yl;
    const u16* Bhg = (which == 0) ? g_wqh : (which == 1) ? g_wkh : g_wvh;
    const u16* Blg = (which == 0) ? g_wql : (which == 1) ? g_wkl : g_wvl;
    const float* bias = (which == 0) ? bq : (which == 1) ? bk : bv;
    const int m0 = blockIdx.y * 128, n0 = blockIdx.x * 128;

    float d[4][4][4] = {};

    stage_prj(Ahg, Alg, Bhg, Blg, sb, m0, n0, 0, tid);
    cpa_commit();
    for (int i = 0; i < 32; ++i) {
        const int p = i & 1;
        if (i + 1 < 32)
            stage_prj(Ahg, Alg, Bhg, Blg, sb + ((i + 1) & 1) * PRJ_STRIDE,
                      m0, n0, (i + 1) * 32, tid);
        cpa_commit();
        cpa_wait1();
        __syncthreads();
        uint32_t Ah = sb + p * PRJ_STRIDE;
        mma_chunk(d, Ah, Ah + PRJ_APB, Ah + PRJ_BOFF, Ah + PRJ_BOFF + PRJ_BPB,
                  PB, wm * 64, wn * 32, lane);
        __syncthreads();
    }

    // epilogue
    #pragma unroll
    for (int mf = 0; mf < 4; ++mf)
        #pragma unroll
        for (int nf = 0; nf < 4; ++nf) {
            int mr = m0 + wm * 64 + mf * 16 + (lane >> 2);
            int nc = n0 + wn * 32 + nf * 8 + ((lane & 3) << 1);
            float2 bv2 = *(const float2*)&bias[nc];
            int bb = mr >> 11, s = mr & (Sz - 1);
            int h = nc >> 6, dd = nc & 63;
            size_t i0 = (((size_t)bb * Hz + h) * Sz + s) * Dz + dd;
            size_t i1 = (((size_t)bb * Hz + h) * Sz + s + 8) * Dz + dd;
            if (which == 2) {
                uint32_t hi, lo;
                split_pack(d[mf][nf][0] + bv2.x, d[mf][nf][1] + bv2.y, hi, lo);
                *(uint32_t*)&g_vh[i0] = hi; *(uint32_t*)&g_vl[i0] = lo;
                split_pack(d[mf][nf][2] + bv2.x, d[mf][nf][3] + bv2.y, hi, lo);
                *(uint32_t*)&g_vh[i1] = hi; *(uint32_t*)&g_vl[i1] = lo;
            } else {
                float* out = (which == 0) ? g_q : g_k;
                *(float2*)&out[i0] = make_float2(d[mf][nf][0] + bv2.x, d[mf][nf][1] + bv2.y);
                *(float2*)&out[i1] = make_float2(d[mf][nf][2] + bv2.x, d[mf][nf][3] + bv2.y);
            }
        }
}

// ---------------------------------------------------------------------------
// Kernel 2: cv[bh] = tanh(t*wc[h]+bc[h]) @ v[bh].
// tanh computed ONCE per (elem, head) at staging into bf16 hi/lo smem planes;
// v staged via cp.async from precomputed planes.  2 heads per CTA.
// 8 warps: head = wid>>2, warp tile 64m x 32n within (128 k-rows x 64 d).
// ---------------------------------------------------------------------------
__global__ __launch_bounds__(256, 1) void cv_mma(
    const float* __restrict__ t_mat, const float* __restrict__ wc,
    const float* __restrict__ bc)
{
    extern __shared__ char smc[];
    const uint32_t sb = smem_u32(smc);
    const int tid = threadIdx.x, lane = tid & 31, wid = tid >> 5;
    const int hg = blockIdx.x, kt = blockIdx.y, b = blockIdx.z;
    const float wc0 = wc[hg * 2], bc0 = bc[hg * 2];
    const float wc1 = wc[hg * 2 + 1], bc1 = bc[hg * 2 + 1];
    const float* Tp = t_mat + (size_t)b * Sz * Sz + (size_t)(kt * 128) * Sz;
    const size_t vb0 = (size_t)(b * Hz + hg * 2) * Sz * Dz;
    const size_t vb1 = vb0 + (size_t)Sz * Dz;

    const int e = wid >> 2, rem = wid & 3;
    const int m0w = (rem >> 1) * 64, n0w = (rem & 1) * 32;

    const int aRow = tid >> 1, aHalf = tid & 1;
    const int bRow = tid >> 3, bSeg = tid & 7;

    float d[4][4][4] = {};

    auto stageA = [&](int s0, uint32_t base) {
        const float* tp = &Tp[(size_t)aRow * Sz + s0 + aHalf * 16];
        #pragma unroll
        for (int u = 0; u < 4; ++u) {
            float4 t4 = *(const float4*)&tp[u * 4];
            uint32_t off = (aRow * PA + aHalf * 16 + u * 4) * 2;
            uint32_t h0, l0, h1, l1;
            split_pack(tanh_fast(fmaf(t4.x, wc0, bc0)), tanh_fast(fmaf(t4.y, wc0, bc0)), h0, l0);
            split_pack(tanh_fast(fmaf(t4.z, wc0, bc0)), tanh_fast(fmaf(t4.w, wc0, bc0)), h1, l1);
            *(uint2*)(smc + (base + off)) = make_uint2(h0, h1);
            *(uint2*)(smc + (base + CV_APB + off)) = make_uint2(l0, l1);
            split_pack(tanh_fast(fmaf(t4.x, wc1, bc1)), tanh_fast(fmaf(t4.y, wc1, bc1)), h0, l0);
            split_pack(tanh_fast(fmaf(t4.z, wc1, bc1)), tanh_fast(fmaf(t4.w, wc1, bc1)), h1, l1);
            *(uint2*)(smc + (base + CV_ABLK + off)) = make_uint2(h0, h1);
            *(uint2*)(smc + (base + CV_ABLK + CV_APB + off)) = make_uint2(l0, l1);
        }
    };
    auto stageB = [&](int s0, uint32_t base) {
        size_t g0 = vb0 + (size_t)(s0 + bRow) * Dz + bSeg * 8;
        size_t g1 = vb1 + (size_t)(s0 + bRow) * Dz + bSeg * 8;
        uint32_t db = sb + base + CV_BOFF + (bRow * PV + bSeg * 8) * 2;
        cpa16(db, g_vh + g0);            cpa16(db + CV_BPB, g_vl + g0);
        cpa16(db + CV_BBLK, g_vh + g1);  cpa16(db + CV_BBLK + CV_BPB, g_vl + g1);
    };

    stageA(0, 0); stageB(0, 0);
    cpa_commit();
    for (int i = 0; i < 64; ++i) {
        const int p = i & 1;
        if (i + 1 < 64) {
            uint32_t nb = ((i + 1) & 1) * CV_STRIDE;
            stageA((i + 1) * 32, nb);
            stageB((i + 1) * 32, nb);
        }
        cpa_commit();
        cpa_wait1();
        __syncthreads();
        uint32_t base = sb + p * CV_STRIDE;
        uint32_t Ah = base + e * CV_ABLK;
        uint32_t Bh = base + CV_BOFF + e * CV_BBLK;
        mma_chunk(d, Ah, Ah + CV_APB, Bh, Bh + CV_BPB, PV, m0w, n0w, lane);
        __syncthreads();
    }

    float* Op = g_cv + (size_t)(b * Hz + hg * 2 + e) * Sz * Dz;
    #pragma unroll
    for (int mf = 0; mf < 4; ++mf)
        #pragma unroll
        for (int nf = 0; nf < 4; ++nf) {
            int row = kt * 128 + m0w + mf * 16 + (lane >> 2);
            int dd  = n0w + nf * 8 + ((lane & 3) << 1);
            *(float2*)&Op[(size_t)row * Dz + dd] = make_float2(d[mf][nf][0], d[mf][nf][1]);
            *(float2*)&Op[(size_t)(row + 8) * Dz + dd] = make_float2(d[mf][nf][2], d[mf][nf][3]);
        }
}

// ---------------------------------------------------------------------------
// Kernel 3: M[bh] = (1/sqrt(D)) * q[bh]^T @ cv[bh]  (64x64, K=2048), split-K x4
// ---------------------------------------------------------------------------
__global__ __launch_bounds__(256) void m_kernel()
{
    const int bh    = blockIdx.x;
    const int split = blockIdx.y;
    const float* Q   = g_q  + (size_t)bh * Sz * Dz;
    const float* CVp = g_cv + (size_t)bh * Sz * Dz;

    __shared__ float As[16][68];
    __shared__ float Bs[16][68];

    const int tid = threadIdx.x;
    const int tx = tid & 15;
    const int ty = tid >> 4;
    const int r  = tid >> 4;
    const int c4 = (tid & 15) * 4;

    float acc[4][4] = {};
    const int sBeg = split * (Sz / 4);

    for (int s0 = sBeg; s0 < sBeg + Sz / 4; s0 += 16) {
        *reinterpret_cast<float4*>(&As[r][c4]) =
            *reinterpret_cast<const float4*>(&Q[(size_t)(s0 + r) * Dz + c4]);
        *reinterpret_cast<float4*>(&Bs[r][c4]) =
            *reinterpret_cast<const float4*>(&CVp[(size_t)(s0 + r) * Dz + c4]);
        __syncthreads();
        #pragma unroll
        for (int kk = 0; kk < 16; ++kk) {
            float4 a = *reinterpret_cast<const float4*>(&As[kk][ty * 4]);
            float4 b = *reinterpret_cast<const float4*>(&Bs[kk][tx * 4]);
            float ar[4] = {a.x, a.y, a.z, a.w};
            float br[4] = {b.x, b.y, b.z, b.w};
            #pragma unroll
            for (int i = 0; i < 4; ++i)
                #pragma unroll
                for (int j = 0; j < 4; ++j)
                    acc[i][j] = fmaf(ar[i], br[j], acc[i][j]);
        }
        __syncthreads();
    }

    float* Mp = g_Mpart + ((size_t)split * BHz + bh) * Dz * Dz;
    #pragma unroll
    for (int i = 0; i < 4; ++i)
        #pragma unroll
        for (int j = 0; j < 4; ++j)
            Mp[(ty * 4 + i) * Dz + tx * 4 + j] = acc[i][j] * 0.125f;
}

// ---------------------------------------------------------------------------
// Kernel 4: att[bh] = k[bh] @ M[bh] -> merged written as bf16 hi/lo planes
// ---------------------------------------------------------------------------
__global__ __launch_bounds__(256) void att_kernel()
{
    const int bh = blockIdx.z;
    const int b  = bh >> 4;
    const int h  = bh & 15;
    const int s0 = blockIdx.y * 64;
    const float* Kp = g_k + (size_t)bh * Sz * Dz;

    __shared__ float Ms[Dz * Dz];
    __shared__ float As[16][68];

    const int tid = threadIdx.x;
    const int tx = tid & 15;
    const int ty = tid >> 4;

    const float4* P0 = reinterpret_cast<const float4*>(g_Mpart + ((size_t)0 * BHz + bh) * Dz * Dz);
    const float4* P1 = reinterpret_cast<const float4*>(g_Mpart + ((size_t)1 * BHz + bh) * Dz * Dz);
    const float4* P2 = reinterpret_cast<const float4*>(g_Mpart + ((size_t)2 * BHz + bh) * Dz * Dz);
    const float4* P3 = reinterpret_cast<const float4*>(g_Mpart + ((size_t)3 * BHz + bh) * Dz * Dz);
    #pragma unroll
    for (int it = 0; it < 4; ++it) {
        int fi = it * 256 + tid;
        float4 a = P0[fi], bb4 = P1[fi], c = P2[fi], dd = P3[fi];
        float4 rr;
        rr.x = a.x + bb4.x + c.x + dd.x;
        rr.y = a.y + bb4.y + c.y + dd.y;
        rr.z = a.z + bb4.z + c.z + dd.z;
        rr.w = a.w + bb4.w + c.w + dd.w;
        reinterpret_cast<float4*>(Ms)[fi] = rr;
    }
    __syncthreads();

    const int aRow = tid >> 2;
    const int aCol = (tid & 3) * 4;

    float acc[4][4] = {};
    #pragma unroll
    for (int kb = 0; kb < 4; ++kb) {
        float4 a4 = *reinterpret_cast<const float4*>(&Kp[(size_t)(s0 + aRow) * Dz + kb * 16 + aCol]);
        As[aCol + 0][aRow] = a4.x;
        As[aCol + 1][aRow] = a4.y;
        As[aCol + 2][aRow] = a4.z;
        As[aCol + 3][aRow] = a4.w;
        __syncthreads();
        #pragma unroll
        for (int kk = 0; kk < 16; ++kk) {
            float4 a = *reinterpret_cast<const float4*>(&As[kk][ty * 4]);
            float4 bm = *reinterpret_cast<const float4*>(&Ms[(kb * 16 + kk) * Dz + tx * 4]);
            float ar[4] = {a.x, a.y, a.z, a.w};
            float br[4] = {bm.x, bm.y, bm.z, bm.w};
            #pragma unroll
            for (int i = 0; i < 4; ++i)
                #pragma unroll
                for (int j = 0; j < 4; ++j)
                    acc[i][j] = fmaf(ar[i], br[j], acc[i][j]);
        }
        __syncthreads();
    }

    #pragma unroll
    for (int i = 0; i < 4; ++i) {
        size_t rowi = ((size_t)b * Sz + s0 + ty * 4 + i) * Cz + h * Dz + tx * 4;
        uint32_t hi, lo;
        split_pack(acc[i][0], acc[i][1], hi, lo);
        *(uint32_t*)&g_mh[rowi] = hi; *(uint32_t*)&g_ml[rowi] = lo;
        split_pack(acc[i][2], acc[i][3], hi, lo);
        *(uint32_t*)&g_mh[rowi + 2] = hi; *(uint32_t*)&g_ml[rowi + 2] = lo;
    }
}

// ---------------------------------------------------------------------------
// Kernel 5: out = mish(merged @ wf + bf).  Same mainloop as proj_mma.
// ---------------------------------------------------------------------------
__global__ __launch_bounds__(256, 1) void final_mma(
    const float* __restrict__ bf, float* __restrict__ out)
{
    extern __shared__ char smc[];
    const uint32_t sb = smem_u32(smc);
    const int tid = threadIdx.x, lane = tid & 31, wid = tid >> 5;
    const int wm = wid & 1, wn = wid >> 1;
    const int m0 = blockIdx.y * 128, n0 = blockIdx.x * 128;

    float d[4][4][4] = {};

    stage_prj(g_mh, g_ml, g_wfh, g_wfl, sb, m0, n0, 0, tid);
    cpa_commit();
    for (int i = 0; i < 32; ++i) {
        const int p = i & 1;
        if (i + 1 < 32)
            stage_prj(g_mh, g_ml, g_wfh, g_wfl, sb + ((i + 1) & 1) * PRJ_STRIDE,
                      m0, n0, (i + 1) * 32, tid);
        cpa_commit();
        cpa_wait1();
        __syncthreads();
        uint32_t Ah = sb + p * PRJ_STRIDE;
        mma_chunk(d, Ah, Ah + PRJ_APB, Ah + PRJ_BOFF, Ah + PRJ_BOFF + PRJ_BPB,
                  PB, wm * 64, wn * 32, lane);
        __syncthreads();
    }

    #pragma unroll
    for (int mf = 0; mf < 4; ++mf)
        #pragma unroll
        for (int nf = 0; nf < 4; ++nf) {
            int mr = m0 + wm * 64 + mf * 16 + (lane >> 2);
            int nc = n0 + wn * 32 + nf * 8 + ((lane & 3) << 1);
            float2 bv2 = *(const float2*)&bf[nc];
            *(float2*)&out[(size_t)mr * Cz + nc] =
                make_float2(mish_f(d[mf][nf][0] + bv2.x), mish_f(d[mf][nf][1] + bv2.y));
            *(float2*)&out[(size_t)(mr + 8) * Cz + nc] =
                make_float2(mish_f(d[mf][nf][2] + bv2.x), mish_f(d[mf][nf][3] + bv2.y));
        }
}

// ---------------------------------------------------------------------------
extern "C" void kernel_launch(void* const* d_in, const int* in_sizes, int n_in,
                              void* d_out, int out_size)
{
    const float* x  = (const float*)d_in[0];
    const float* y  = (const float*)d_in[1];
    const float* t  = (const float*)d_in[2];
    const float* bq = (const float*)d_in[4];
    const float* bk = (const float*)d_in[6];
    const float* bv = (const float*)d_in[8];
    const float* wc = (const float*)d_in[9];
    const float* bc = (const float*)d_in[10];
    const float* bf = (const float*)d_in[12];
    float* out = (float*)d_out;

    cudaFuncSetAttribute(proj_mma,  cudaFuncAttributeMaxDynamicSharedMemorySize, PROJ_SMEM);
    cudaFuncSetAttribute(cv_mma,    cudaFuncAttributeMaxDynamicSharedMemorySize, CV_SMEM);
    cudaFuncSetAttribute(final_mma, cudaFuncAttributeMaxDynamicSharedMemorySize, PROJ_SMEM);

    // resolve device-global plane addresses
    u16 *xh, *xl, *yh, *yl, *wqh, *wql, *wkh, *wkl, *wvh, *wvl, *wfh, *wfl;
    cudaGetSymbolAddress((void**)&xh,  g_xh);  cudaGetSymbolAddress((void**)&xl,  g_xl);
    cudaGetSymbolAddress((void**)&yh,  g_yh);  cudaGetSymbolAddress((void**)&yl,  g_yl);
    cudaGetSymbolAddress((void**)&wqh, g_wqh); cudaGetSymbolAddress((void**)&wql, g_wql);
    cudaGetSymbolAddress((void**)&wkh, g_wkh); cudaGetSymbolAddress((void**)&wkl, g_wkl);
    cudaGetSymbolAddress((void**)&wvh, g_wvh); cudaGetSymbolAddress((void**)&wvl, g_wvl);
    cudaGetSymbolAddress((void**)&wfh, g_wfh); cudaGetSymbolAddress((void**)&wfl, g_wfl);

    const int nAct = Bz * Sz * Cz;   // 4M
    const int nW   = Cz * Cz;        // 1M
    cvt_kernel<<<nAct / 1024, 256>>>(x, xh, xl, nAct);
    cvt_kernel<<<nAct / 1024, 256>>>(y, yh, yl, nAct);
    cvt_kernel<<<nW   / 1024, 256>>>((const float*)d_in[3],  wqh, wql, nW);
    cvt_kernel<<<nW   / 1024, 256>>>((const float*)d_in[5],  wkh, wkl, nW);
    cvt_kernel<<<nW   / 1024, 256>>>((const float*)d_in[7],  wvh, wvl, nW);
    cvt_kernel<<<nW   / 1024, 256>>>((const float*)d_in[11], wfh, wfl, nW);

    // q,k,v projections
    proj_mma<<<dim3(Cz / 128, (Bz * Sz) / 128, 3), 256, PROJ_SMEM>>>(bq, bk, bv);
    // cv = tanh(t*wc+bc) @ v  (c never materialized)
    cv_mma<<<dim3(Hz / 2, Sz / 128, Bz), 256, CV_SMEM>>>(t, wc, bc);
    // M = q^T @ cv / sqrt(D), split-K x4
    m_kernel<<<dim3(BHz, 4), 256>>>();
    // att = k @ M -> merged bf16 planes
    att_kernel<<<dim3(1, Sz / 64, BHz), 256>>>();
    // out = mish(merged @ wf + bf)
    final_mma<<<dim3(Cz / 128, (Bz * Sz) / 128), 256, PROJ_SMEM>>>(bf, out);
}